// round 7
// baseline (speedup 1.0000x reference)
#include <cuda_runtime.h>
#include <cuda_bf16.h>
#include <cstdint>
#include <math.h>

#define TAU 0.5f
#define B 16
#define H 96
#define W 96
#define NPIX (H * W)
#define NS 8                 // query slices per (image, direction)
#define NBLK (2 * B * NS)    // 256 blocks
#define NT 768               // 24 warps
#define NW (NT / 32)
#define SLICE_PIX (NPIX / NS)   // 1152
#define BIG 100000

// static device scratch (no allocation; zero-initialized at module load)
__device__ int g_maxAB[B];
__device__ int g_maxBA[B];
__device__ int g_anyP[B];
__device__ int g_anyL[B];
__device__ int g_done = 0;

// exact full search over target bitmask (rare path / empty-target path)
__device__ __noinline__ int full_search(const uint32_t* mtp, int x, int y, int best)
{
    for (int yy = 0; yy < H; yy++) {
        int dy2 = (yy - y) * (yy - y);
        if (dy2 >= best) continue;
        #pragma unroll
        for (int w = 0; w < 3; w++) {
            uint32_t m = mtp[yy * 5 + 1 + w];
            while (m) {
                int bpos = __ffs(m) - 1; m &= m - 1;
                int dx = w * 32 + bpos - x;
                best = min(best, dy2 + dx * dx);
            }
        }
    }
    return best;
}

__global__ void __launch_bounds__(NT, 1)
hd_all(const float* __restrict__ pred,
       const float* __restrict__ tgt,
       float* __restrict__ out)
{
    // target row bitmasks, padded: [y][0]=0, [y][1..3]=bits, [y][4]=0
    __shared__ uint32_t mtp[H * 5];
    __shared__ int s_red[NW];
    __shared__ int s_last;

    const int bx    = blockIdx.x;
    const int slice = bx & (NS - 1);
    const int gd    = bx >> 3;         // 0..31
    const int img   = gd >> 1;
    const int dir   = gd & 1;
    const int tid   = threadIdx.x;
    const int lane  = tid & 31;
    const int wrp   = tid >> 5;

    // dir 0: query = pred, target = label  -> d_ab
    // dir 1: query = label, target = pred  -> d_ba
    const float* srcQ = dir ? (tgt  + img * NPIX) : (pred + img * NPIX);
    const float* srcT = dir ? (pred + img * NPIX) : (tgt  + img * NPIX);

    if (tid < H) { mtp[tid * 5 + 0] = 0u; mtp[tid * 5 + 4] = 0u; }

    // ---- phase 1: build full target row-bitmask via ballots ----
    unsigned at = 0;
    #pragma unroll
    for (int k = 0; k < NPIX / NT; k++) {
        int i = tid + k * NT;
        unsigned bt = __ballot_sync(0xFFFFFFFFu, srcT[i] >= TAU);
        at |= bt;
        if (lane == 0) {
            int wi = i >> 5;               // word index = y*3 + xw
            int y = wi / 3, xw = wi - y * 3;
            mtp[y * 5 + 1 + xw] = bt;
        }
    }
    // query slice loads (independent of the ballots; only this block's slice)
    const int sbase = slice * SLICE_PIX;
    float qv0 = srcQ[sbase + tid];
    float qv1 = 0.0f;
    if (tid < SLICE_PIX - NT) qv1 = srcQ[sbase + NT + tid];

    if (lane == 0 && at) atomicOr(dir ? &g_anyP[img] : &g_anyL[img], 1);
    __syncthreads();

    // ---- phase 2: 1-2 query pixels per thread, 5x5 window (exact when best<=8) ----
    const int x   = tid % W;               // (SLICE_PIX and NT are multiples of W)
    const int y0  = slice * (SLICE_PIX / W) + tid / W;
    const int pos = x + 30;                // window start (x-2) biased by pad word
    const int q   = pos >> 5;
    const int sh  = pos & 31;

    auto tval = [&](int y) -> int {
        if ((unsigned)y >= (unsigned)H) return BIG;
        uint32_t lo = mtp[y * 5 + q], hi = mtp[y * 5 + q + 1];
        uint32_t b = __funnelshift_r(lo, hi, sh) & 31u;
        return (b & 4u) ? 0 : ((b & 10u) ? 1 : ((b & 17u) ? 4 : BIG));
    };
    auto window = [&](int y) -> int {
        int c  = tval(y);
        int p1 = min(tval(y - 1), tval(y + 1));
        int p2 = min(tval(y - 2), tval(y + 2));
        int best = min(c, min(p1 + 1, p2 + 4));
        if (best > 8) best = full_search(mtp, x, y, best);   // exact, ~never taken
        return best;
    };

    int lmax = 0;
    if (qv0 >= TAU) lmax = window(y0);
    if (tid < SLICE_PIX - NT && qv1 >= TAU)
        lmax = max(lmax, window(y0 + (NT / W)));

    // ---- block max reduction -> global atomicMax ----
    #pragma unroll
    for (int o = 16; o > 0; o >>= 1)
        lmax = max(lmax, __shfl_xor_sync(0xFFFFFFFFu, lmax, o));
    if (lane == 0) s_red[wrp] = lmax;
    __syncthreads();
    if (tid < 32) {
        int v = (tid < NW) ? s_red[tid] : 0;
        #pragma unroll
        for (int o = 16; o > 0; o >>= 1)
            v = max(v, __shfl_xor_sync(0xFFFFFFFFu, v, o));
        if (tid == 0) {
            atomicMax(dir ? &g_maxBA[img] : &g_maxAB[img], v);
            __threadfence();
            int old = atomicAdd(&g_done, 1);
            s_last = (old == NBLK - 1);
        }
    }
    __syncthreads();
    if (!s_last) return;
    __threadfence();

    // ---------------- finalize (exactly one block) ----------------
    __shared__ float hd[B];
    __shared__ int needs[B];    // 0 normal, 1 diam(pred), 2 diam(label)
    if (tid < B) {
        int aa = g_anyP[tid], bb = g_anyL[tid];
        if (aa && bb) {
            hd[tid] = sqrtf((float)max(g_maxAB[tid], g_maxBA[tid]));
            needs[tid] = 0;
        } else if (!aa && !bb) {
            hd[tid] = 0.0f;
            needs[tid] = 0;
        } else {
            needs[tid] = aa ? 1 : 2;
        }
    }
    __syncthreads();

    // reset scratch for next graph replay (values already consumed above)
    if (tid < B) {
        g_maxAB[tid] = 0; g_maxBA[tid] = 0;
        g_anyP[tid] = 0;  g_anyL[tid] = 0;
    }
    if (tid == 0) g_done = 0;

    // empty-set fallback: diameter (formal correctness; never runs on this data)
    __shared__ int s_diam;
    for (int im = 0; im < B; im++) {
        if (needs[im]) {
            const float* src = (needs[im] == 1) ? (pred + im * NPIX)
                                                : (tgt  + im * NPIX);
            if (tid == 0) s_diam = 0;
            __syncthreads();
            int best = 0;
            for (int p = tid; p < NPIX; p += NT) {
                if (src[p] >= TAU) {
                    int py = p / W, px = p - (p / W) * W;
                    for (int qq = 0; qq < NPIX; qq++) {
                        if (src[qq] >= TAU) {
                            int dy = py - qq / W;
                            int dxx = px - (qq - (qq / W) * W);
                            best = max(best, dy * dy + dxx * dxx);
                        }
                    }
                }
            }
            atomicMax(&s_diam, best);
            __syncthreads();
            if (tid == 0) hd[im] = sqrtf((float)s_diam);
            __syncthreads();
        }
    }

    if (tid == 0) {
        float s = 0.0f;
        #pragma unroll
        for (int i = 0; i < B; i++) s += hd[i];
        out[0] = s * (1.0f / B);
    }
}

// ---------------------------------------------------------------------------
extern "C" void kernel_launch(void* const* d_in, const int* in_sizes, int n_in,
                              void* d_out, int out_size)
{
    const float* pred = (const float*)d_in[0];
    const float* tgt  = (const float*)d_in[1];
    float* out = (float*)d_out;

    hd_all<<<NBLK, NT>>>(pred, tgt, out);
}

// round 8
// speedup vs baseline: 1.3488x; 1.3488x over previous
#include <cuda_runtime.h>
#include <cuda_bf16.h>
#include <cstdint>
#include <math.h>

#define TAU 0.5f
#define B 16
#define H 96
#define W 96
#define NPIX (H * W)
#define NB (2 * B)        // 32 blocks: (image, direction)
#define NT 1024           // 32 warps
#define NWRP (NT / 32)
#define NWORDS (H * 3)    // 288 mask words per image
#define BIG 100000

// static device scratch (no allocation)
__device__ int g_maxAB[B];
__device__ int g_maxBA[B];
__device__ int g_anyP[B];   // pred nonempty
__device__ int g_anyL[B];   // label nonempty
__device__ int g_done = 0;

// exact search over target bitmask for one pixel (rare / empty-target path)
__device__ __noinline__ int full_search(const uint32_t* mtp, int x, int y)
{
    int best = BIG;
    for (int yy = 0; yy < H; yy++) {
        int dy2 = (yy - y) * (yy - y);
        if (dy2 >= best) continue;
        #pragma unroll
        for (int w = 0; w < 3; w++) {
            uint32_t m = mtp[(yy + 2) * 5 + 1 + w];
            while (m) {
                int bp = __ffs(m) - 1; m &= m - 1;
                int dx = w * 32 + bp - x;
                best = min(best, dy2 + dx * dx);
            }
        }
    }
    return best;
}

__global__ void __launch_bounds__(NT, 1)
hd_all(const float* __restrict__ pred,
       const float* __restrict__ tgt,
       float* __restrict__ out)
{
    // target mask, padded: rows -2..H+1 (index r+2), words [0, w0,w1,w2, 0]
    __shared__ uint32_t mtp[(H + 4) * 5];
    __shared__ uint32_t qw[NWORDS];
    __shared__ int s_red[NWRP], s_any[NWRP];
    __shared__ int s_last;

    const int bx   = blockIdx.x;
    const int img  = bx >> 1;
    const int dir  = bx & 1;
    const int tid  = threadIdx.x;
    const int lane = tid & 31;
    const int wrp  = tid >> 5;

    // dir 0: query=pred, target=label (d_ab); dir 1: reverse (d_ba)
    const float* srcQ = dir ? (tgt  + img * NPIX) : (pred + img * NPIX);
    const float* srcT = dir ? (pred + img * NPIX) : (tgt  + img * NPIX);

    // zero ONLY pad words (never touched by ballot writes -> no race)
    if (tid < (H + 4) * 5) {
        int r = tid / 5, c = tid - r * 5;
        if (r < 2 || r >= H + 2 || c == 0 || c == 4) mtp[tid] = 0u;
    }

    // ---- phase 1: build both bitmasks via ballots (9 iters, coalesced) ----
    #pragma unroll
    for (int k = 0; k < NPIX / NT; k++) {
        int i = tid + k * NT;
        unsigned bt = __ballot_sync(0xFFFFFFFFu, srcT[i] >= TAU);
        unsigned bq = __ballot_sync(0xFFFFFFFFu, srcQ[i] >= TAU);
        if (lane == 0) {
            int wi = wrp + NWRP * k;          // word index = y*3 + xw
            int y = wi / 3, xw = wi - y * 3;
            mtp[(y + 2) * 5 + 1 + xw] = bt;
            qw[wi] = bq;
        }
    }
    __syncthreads();

    // ---- phase 2: bitwise 5x5 dilation, one word (32 pixels) per thread ----
    int pmax = 0;    // per-thread max d2 (query side)
    int tany = 0;    // OR of target words (each word owned by exactly one thread)
    if (tid < NWORDS) {
        const int y  = tid / 3;
        const int wc = tid - y * 3;
        uint32_t C[5], h1[5], h2[5];
        #pragma unroll
        for (int j = 0; j < 5; j++) {
            uint32_t l = mtp[(y + j) * 5 + wc];
            uint32_t c = mtp[(y + j) * 5 + wc + 1];
            uint32_t r = mtp[(y + j) * 5 + wc + 2];
            C[j]  = c;
            h1[j] = __funnelshift_l(l, c, 1) | __funnelshift_r(c, r, 1);
            h2[j] = __funnelshift_l(l, c, 2) | __funnelshift_r(c, r, 2);
        }
        uint32_t D0 = C[2];
        uint32_t D1 = D0 | h1[2] | C[1] | C[3];
        uint32_t D2 = D1 | h1[1] | h1[3];
        uint32_t D4 = D2 | h2[2] | C[0] | C[4];
        uint32_t D5 = D4 | h2[1] | h2[3] | h1[0] | h1[4];
        uint32_t D8 = D5 | h2[0] | h2[4];

        uint32_t q = qw[tid];
        tany = (D0 != 0u);
        pmax = (q & ~D5) ? 8 : (q & ~D4) ? 5 : (q & ~D2) ? 4
             : (q & ~D1) ? 2 : (q & ~D0) ? 1 : 0;

        uint32_t fb = q & ~D8;              // d2 >= 9: exact fallback (~never)
        while (fb) {
            int bp = __ffs(fb) - 1; fb &= fb - 1;
            pmax = max(pmax, full_search(mtp, wc * 32 + bp, y));
        }
    }

    // ---- block reduction (max d2, any-target) ----
    #pragma unroll
    for (int o = 16; o > 0; o >>= 1) {
        pmax = max(pmax, __shfl_xor_sync(0xFFFFFFFFu, pmax, o));
        tany |= __shfl_xor_sync(0xFFFFFFFFu, tany, o);
    }
    if (lane == 0) { s_red[wrp] = pmax; s_any[wrp] = tany; }
    __syncthreads();
    if (tid < 32) {
        int v = (tid < NWRP) ? s_red[tid] : 0;
        int a = (tid < NWRP) ? s_any[tid] : 0;
        #pragma unroll
        for (int o = 16; o > 0; o >>= 1) {
            v = max(v, __shfl_xor_sync(0xFFFFFFFFu, v, o));
            a |= __shfl_xor_sync(0xFFFFFFFFu, a, o);
        }
        if (tid == 0) {
            // this block is the sole owner of (img,dir): plain stores
            if (dir == 0) { g_maxAB[img] = v; g_anyL[img] = a; }
            else          { g_maxBA[img] = v; g_anyP[img] = a; }
            __threadfence();
            int old = atomicAdd(&g_done, 1);
            s_last = (old == NB - 1);
        }
    }
    __syncthreads();
    if (!s_last) return;
    __threadfence();

    // ---------------- finalize (exactly one block) ----------------
    __shared__ float hd[B];
    __shared__ int needs[B];    // 0 normal, 1 diam(pred), 2 diam(label)
    if (tid < B) {
        int aa = g_anyP[tid], bb = g_anyL[tid];
        if (aa && bb) {
            hd[tid] = sqrtf((float)max(g_maxAB[tid], g_maxBA[tid]));
            needs[tid] = 0;
        } else if (!aa && !bb) {
            hd[tid] = 0.0f;
            needs[tid] = 0;
        } else {
            needs[tid] = aa ? 1 : 2;
        }
    }
    if (tid == 0) g_done = 0;   // reset for next graph replay
    __syncthreads();

    // empty-set fallback: diameter (formal correctness; never runs on this data)
    __shared__ int s_diam;
    for (int im = 0; im < B; im++) {
        if (needs[im]) {
            const float* src = (needs[im] == 1) ? (pred + im * NPIX)
                                                : (tgt  + im * NPIX);
            if (tid == 0) s_diam = 0;
            __syncthreads();
            int best = 0;
            for (int p = tid; p < NPIX; p += NT) {
                if (src[p] >= TAU) {
                    int py = p / W, px = p - (p / W) * W;
                    for (int qq = 0; qq < NPIX; qq++) {
                        if (src[qq] >= TAU) {
                            int dy = py - qq / W;
                            int dxx = px - (qq - (qq / W) * W);
                            best = max(best, dy * dy + dxx * dxx);
                        }
                    }
                }
            }
            atomicMax(&s_diam, best);
            __syncthreads();
            if (tid == 0) hd[im] = sqrtf((float)s_diam);
            __syncthreads();
        }
    }

    if (tid == 0) {
        float s = 0.0f;
        #pragma unroll
        for (int i = 0; i < B; i++) s += hd[i];
        out[0] = s * (1.0f / B);
    }
}

// ---------------------------------------------------------------------------
extern "C" void kernel_launch(void* const* d_in, const int* in_sizes, int n_in,
                              void* d_out, int out_size)
{
    const float* pred = (const float*)d_in[0];
    const float* tgt  = (const float*)d_in[1];
    float* out = (float*)d_out;

    hd_all<<<NB, NT>>>(pred, tgt, out);
}